// round 3
// baseline (speedup 1.0000x reference)
#include <cuda_runtime.h>

#define N_NODES 10000
#define D_FEAT  128
#define BATCH   8192
#define K_NEIGH 25
#define KB      5          // batch width for feat loads (25 = 5 x 5)

__global__ void __launch_bounds__(256) mean_agg_kernel(
    const int*   __restrict__ nodes,      // [BATCH]           (int32)
    const int*   __restrict__ neigh_idx,  // [BATCH, K]        (int32)
    const float* __restrict__ feat,       // [N_NODES, D_FEAT]
    const float* __restrict__ adj,        // [N_NODES, N_NODES]
    const float* __restrict__ fsim,       // [N_NODES, N_NODES]
    float*       __restrict__ out)        // [BATCH, D_FEAT]
{
    const int warp = (blockIdx.x * blockDim.x + threadIdx.x) >> 5;
    const int lane = threadIdx.x & 31;
    if (warp >= BATCH) return;

    const int row = nodes[warp];

    // Lanes 0..24 each gather one neighbor weight.
    int   my_idx = 0;
    float my_w   = 0.0f;
    if (lane < K_NEIGH) {
        my_idx = neigh_idx[warp * K_NEIGH + lane];
        const unsigned base = (unsigned)row * N_NODES + (unsigned)my_idx;
        my_w = adj[base] + fsim[base];
    }

    // denom = sum of weights (lanes >= 25 hold 0)
    float denom = my_w;
    #pragma unroll
    for (int off = 16; off; off >>= 1)
        denom += __shfl_xor_sync(0xffffffffu, denom, off);

    // Weighted feature accumulation. Each lane owns 4 contiguous dims.
    // Explicit 5-wide batches of independent float4 loads -> high MLP.
    float4 acc = make_float4(0.f, 0.f, 0.f, 0.f);
    const float4* __restrict__ feat4 = (const float4*)feat;

    #pragma unroll
    for (int kb = 0; kb < K_NEIGH; kb += KB) {
        float4 f[KB];
        float  w[KB];
        #pragma unroll
        for (int j = 0; j < KB; j++) {
            const int   ik = __shfl_sync(0xffffffffu, my_idx, kb + j);
            w[j]           = __shfl_sync(0xffffffffu, my_w,   kb + j);
            f[j]           = feat4[(unsigned)ik * (D_FEAT / 4) + lane];
        }
        #pragma unroll
        for (int j = 0; j < KB; j++) {
            acc.x += w[j] * f[j].x;
            acc.y += w[j] * f[j].y;
            acc.z += w[j] * f[j].z;
            acc.w += w[j] * f[j].w;
        }
    }

    const float inv = 1.0f / denom;
    float4 o;
    o.x = acc.x * inv;
    o.y = acc.y * inv;
    o.z = acc.z * inv;
    o.w = acc.w * inv;
    ((float4*)out)[warp * (D_FEAT / 4) + lane] = o;
}

extern "C" void kernel_launch(void* const* d_in, const int* in_sizes, int n_in,
                              void* d_out, int out_size)
{
    const int*   nodes = (const int*)d_in[0];
    const int*   neigh = (const int*)d_in[1];
    const float* feat  = (const float*)d_in[2];
    const float* adj   = (const float*)d_in[3];
    const float* fsim  = (const float*)d_in[4];
    float*       out   = (float*)d_out;

    const int threads = 256;                                   // 8 warps/block
    const int blocks  = (BATCH * 32 + threads - 1) / threads;  // 1024 blocks
    mean_agg_kernel<<<blocks, threads>>>(nodes, neigh, feat, adj, fsim, out);
}

// round 4
// speedup vs baseline: 1.0025x; 1.0025x over previous
#include <cuda_runtime.h>

#define N_NODES 10000
#define D_FEAT  128
#define BATCH   8192
#define K_NEIGH 25
#define B1      13
#define B2      12

__global__ void __launch_bounds__(256) mean_agg_kernel(
    const int*   __restrict__ nodes,      // [BATCH]           (int32)
    const int*   __restrict__ neigh_idx,  // [BATCH, K]        (int32)
    const float* __restrict__ feat,       // [N_NODES, D_FEAT]
    const float* __restrict__ adj,        // [N_NODES, N_NODES]
    const float* __restrict__ fsim,       // [N_NODES, N_NODES]
    float*       __restrict__ out)        // [BATCH, D_FEAT]
{
    const int warp = (blockIdx.x * blockDim.x + threadIdx.x) >> 5;
    const int lane = threadIdx.x & 31;
    if (warp >= BATCH) return;

    const int row = nodes[warp];

    // Lanes 0..24 each gather one neighbor weight (random DRAM access).
    int   my_idx = 0;
    float my_w   = 0.0f;
    if (lane < K_NEIGH) {
        my_idx = neigh_idx[warp * K_NEIGH + lane];
        const unsigned base = (unsigned)row * N_NODES + (unsigned)my_idx;
        my_w = adj[base] + fsim[base];
    }

    // denom = sum of weights (lanes >= 25 hold 0)
    float denom = my_w;
    #pragma unroll
    for (int off = 16; off; off >>= 1)
        denom += __shfl_xor_sync(0xffffffffu, denom, off);

    const float4* __restrict__ feat4 = (const float4*)feat;
    const float4* lane_base = feat4 + lane;

    float4 acc = make_float4(0.f, 0.f, 0.f, 0.f);

    // ---- Batch 1: 13 independent float4 loads forced in flight ----
    {
        const float4* p[B1];
        #pragma unroll
        for (int j = 0; j < B1; j++) {
            const int ik = __shfl_sync(0xffffffffu, my_idx, j);
            p[j] = lane_base + (unsigned)ik * (D_FEAT / 4);
        }
        float4 f[B1];
        #pragma unroll
        for (int j = 0; j < B1; j++) {
            asm volatile("ld.global.nc.v4.f32 {%0,%1,%2,%3}, [%4];"
                         : "=f"(f[j].x), "=f"(f[j].y), "=f"(f[j].z), "=f"(f[j].w)
                         : "l"(p[j]));
        }
        #pragma unroll
        for (int j = 0; j < B1; j++) {
            const float wk = __shfl_sync(0xffffffffu, my_w, j);
            acc.x += wk * f[j].x;
            acc.y += wk * f[j].y;
            acc.z += wk * f[j].z;
            acc.w += wk * f[j].w;
        }
    }

    // ---- Batch 2: remaining 12 loads ----
    {
        const float4* p[B2];
        #pragma unroll
        for (int j = 0; j < B2; j++) {
            const int ik = __shfl_sync(0xffffffffu, my_idx, B1 + j);
            p[j] = lane_base + (unsigned)ik * (D_FEAT / 4);
        }
        float4 f[B2];
        #pragma unroll
        for (int j = 0; j < B2; j++) {
            asm volatile("ld.global.nc.v4.f32 {%0,%1,%2,%3}, [%4];"
                         : "=f"(f[j].x), "=f"(f[j].y), "=f"(f[j].z), "=f"(f[j].w)
                         : "l"(p[j]));
        }
        #pragma unroll
        for (int j = 0; j < B2; j++) {
            const float wk = __shfl_sync(0xffffffffu, my_w, B1 + j);
            acc.x += wk * f[j].x;
            acc.y += wk * f[j].y;
            acc.z += wk * f[j].z;
            acc.w += wk * f[j].w;
        }
    }

    const float inv = 1.0f / denom;
    float4 o;
    o.x = acc.x * inv;
    o.y = acc.y * inv;
    o.z = acc.z * inv;
    o.w = acc.w * inv;
    ((float4*)out)[warp * (D_FEAT / 4) + lane] = o;
}

extern "C" void kernel_launch(void* const* d_in, const int* in_sizes, int n_in,
                              void* d_out, int out_size)
{
    const int*   nodes = (const int*)d_in[0];
    const int*   neigh = (const int*)d_in[1];
    const float* feat  = (const float*)d_in[2];
    const float* adj   = (const float*)d_in[3];
    const float* fsim  = (const float*)d_in[4];
    float*       out   = (float*)d_out;

    const int threads = 256;                                   // 8 warps/block
    const int blocks  = (BATCH * 32 + threads - 1) / threads;  // 1024 blocks
    mean_agg_kernel<<<blocks, threads>>>(nodes, neigh, feat, adj, fsim, out);
}